// round 5
// baseline (speedup 1.0000x reference)
#include <cuda_runtime.h>
#include <math.h>
#include <limits.h>

#define NB 128
#define NV 128000
#define N4 (NV/4)
#define BPR 32
#define CHUNK4 (N4/BPR)   /* 1000 float4 per block */
#define TINYV 6.103515625e-05f
#define SEPS 1e-05f
#define CAP 4096
#define SCAP 256

__device__ unsigned char g_mask[(size_t)NB*NV];
__device__ unsigned g_rowmax[NB];
__device__ int g_candcnt[NB];
__device__ float g_cand[NB*CAP];
__device__ int g_cidx[NB*CAP];
__device__ float g_params[NB*8];

__device__ __forceinline__ unsigned ofl(float f){
  unsigned u = __float_as_uint(f);
  return (u & 0x80000000u) ? ~u : (u | 0x80000000u);
}
__device__ __forceinline__ float ifl(unsigned u){
  return __uint_as_float((u & 0x80000000u) ? (u & 0x7FFFFFFFu) : ~u);
}
__device__ __forceinline__ float cutf(float M){
  return M - 0.38f*fabsf(M) - 0.5f;
}
/* bit-exact mirror of the reference arithmetic: l/pen (or l*pen), -pp, /temp */
__device__ __forceinline__ float xform(float l, unsigned mb, float rp, float pp, float tv){
  float x = l;
  if (mb){
    x = (l > 0.f) ? __fdiv_rn(l, rp) : __fmul_rn(l, rp);
    if (mb & 2u) x = __fsub_rn(x, pp);
  }
  return __fdiv_rn(x, tv);
}
__device__ __forceinline__ float4 compute_x(float4 l, unsigned m, float rp, float pp, float tv){
  float4 r;
  r.x = xform(l.x, (m      ) & 0xFFu, rp, pp, tv);
  r.y = xform(l.y, (m >>  8) & 0xFFu, rp, pp, tv);
  r.z = xform(l.z, (m >> 16) & 0xFFu, rp, pp, tv);
  r.w = xform(l.w, (m >> 24) & 0xFFu, rp, pp, tv);
  return r;
}

__global__ void k_zero(){
  size_t i0 = (size_t)blockIdx.x*blockDim.x + threadIdx.x;
  uint4* p = (uint4*)g_mask;
  size_t n = (size_t)NB*NV/16;
  uint4 z = make_uint4(0u,0u,0u,0u);
  for (size_t i = i0; i < n; i += (size_t)gridDim.x*blockDim.x) p[i] = z;
  if (i0 < NB){ g_rowmax[i0] = 0u; g_candcnt[i0] = 0; }
}

/* tokens are int32 on device */
__global__ void k_scatter(const int* __restrict__ toks, int L, int bit){
  int i = blockIdx.x*blockDim.x + threadIdx.x;
  if (i >= NB*L) return;
  int row = i / L;
  int t = toks[i];
  if (t >= 0 && t < NV){
    unsigned char* m = &g_mask[(size_t)row*NV + (size_t)t];
    *m = (unsigned char)(*m | bit);
  }
}

__global__ __launch_bounds__(256) void k_max(
  const float* __restrict__ logits, const float* __restrict__ presence,
  const float* __restrict__ rep, const float* __restrict__ temp)
{
  __shared__ float s_red[8];
  int row = blockIdx.y;
  float rp = rep[row], pp = presence[row];
  float tv = temp[row]; if (tv < SEPS) tv = 1.f;
  int base = blockIdx.x*CHUNK4;
  const float4* l4 = ((const float4*)(logits + (size_t)row*NV)) + base;
  const unsigned* m4 = ((const unsigned*)(g_mask + (size_t)row*NV)) + base;
  float mymax = -INFINITY;
  for (int i = threadIdx.x; i < CHUNK4; i += 256){
    float4 x = compute_x(l4[i], m4[i], rp, pp, tv);
    mymax = fmaxf(fmaxf(mymax, fmaxf(x.x, x.y)), fmaxf(x.z, x.w));
  }
  #pragma unroll
  for (int o = 16; o > 0; o >>= 1) mymax = fmaxf(mymax, __shfl_xor_sync(0xFFFFFFFFu, mymax, o));
  if ((threadIdx.x & 31) == 0) s_red[threadIdx.x >> 5] = mymax;
  __syncthreads();
  if (threadIdx.x == 0){
    float v = s_red[0];
    #pragma unroll
    for (int w = 1; w < 8; w++) v = fmaxf(v, s_red[w]);
    atomicMax(&g_rowmax[row], ofl(v));
  }
}

__global__ __launch_bounds__(256) void k_gather(
  const float* __restrict__ logits, const float* __restrict__ presence,
  const float* __restrict__ rep, const float* __restrict__ temp)
{
  int row = blockIdx.y;
  float rp = rep[row], pp = presence[row];
  float tv = temp[row]; if (tv < SEPS) tv = 1.f;
  float M = ifl(g_rowmax[row]);
  float cut = cutf(M);
  int base = blockIdx.x*CHUNK4;
  const float4* l4 = ((const float4*)(logits + (size_t)row*NV)) + base;
  const unsigned* m4 = ((const unsigned*)(g_mask + (size_t)row*NV)) + base;
  for (int i = threadIdx.x; i < CHUNK4; i += 256){
    float4 x = compute_x(l4[i], m4[i], rp, pp, tv);
    float v[4] = {x.x, x.y, x.z, x.w};
    #pragma unroll
    for (int j = 0; j < 4; j++){
      if (v[j] >= cut){
        int p = atomicAdd(&g_candcnt[row], 1);
        if (p < CAP){ g_cand[row*CAP + p] = v[j]; g_cidx[row*CAP + p] = (base + i)*4 + j; }
      }
    }
  }
}

__global__ __launch_bounds__(256) void k_select(
  const float* __restrict__ logits, const float* __restrict__ presence,
  const float* __restrict__ rep, const float* __restrict__ temp,
  const int* __restrict__ topk, const float* __restrict__ topp)
{
  __shared__ float s_cand[CAP];
  __shared__ int s_cidx[CAP];
  __shared__ unsigned s_hist[256];
  __shared__ float s_small[SCAP];
  __shared__ float s_e[SCAP];
  __shared__ unsigned s_cnt;
  __shared__ int s_sel, s_want;

  int row = blockIdx.x, tid = threadIdx.x;
  float M = ifl(g_rowmax[row]);
  int kneed = topk[row]; if (kneed < 1) kneed = 1; if (kneed > NV) kneed = NV;
  float tp = topp[row];
  int count = g_candcnt[row];

  if (count >= kneed && count <= CAP){
    for (int i = tid; i < count; i += 256){
      s_cand[i] = g_cand[row*CAP + i];
      s_cidx[i] = g_cidx[row*CAP + i];
    }
  } else {
    /* fallback: bracketed threshold search (cold path) */
    float rp = rep[row], pp = presence[row];
    float tv = temp[row]; if (tv < SEPS) tv = 1.f;
    const float4* l4 = (const float4*)(logits + (size_t)row*NV);
    const unsigned* m4 = (const unsigned*)(g_mask + (size_t)row*NV);
    float delta = 0.38f*fabsf(M) + 0.5f;
    float dlo = 0.f, dhi = -1.f;
    if (count < kneed){ dlo = delta; delta *= 2.f; }
    else              { dhi = delta; delta *= 0.5f; }
    for (int it = 0; it < 64; it++){
      float c2 = M - delta;
      if (tid == 0) s_cnt = 0;
      __syncthreads();
      for (int i = tid; i < N4; i += 256){
        float4 x = compute_x(l4[i], m4[i], rp, pp, tv);
        float v[4] = {x.x, x.y, x.z, x.w};
        #pragma unroll
        for (int j = 0; j < 4; j++){
          if (v[j] >= c2){
            unsigned id = atomicAdd(&s_cnt, 1u);
            if (id < CAP){ s_cand[id] = v[j]; s_cidx[id] = i*4 + j; }
          }
        }
      }
      __syncthreads();
      count = (int)s_cnt;
      __syncthreads();
      if (count >= kneed && count <= CAP) break;
      if (count < kneed){ dlo = delta; delta = (dhi > 0.f) ? 0.5f*(delta + dhi) : delta*2.f; }
      else              { dhi = delta; delta = 0.5f*(dlo + delta); }
    }
    if (count > CAP) count = CAP;
    if (count < kneed) kneed = count;
  }
  __syncthreads();

  /* radix-select k-th largest value */
  unsigned prefix = 0; int want = kneed;
  for (int shift = 24; shift >= 0; shift -= 8){
    s_hist[tid] = 0;
    __syncthreads();
    unsigned himask = (shift == 24) ? 0u : (0xFFFFFFFFu << (shift + 8));
    for (int i = tid; i < count; i += 256){
      unsigned ou = ofl(s_cand[i]);
      if ((ou & himask) == prefix) atomicAdd(&s_hist[(ou >> shift) & 255u], 1u);
    }
    __syncthreads();
    if (tid == 0){
      int c = 0, b = 255;
      for (; b > 0; b--){
        int h = (int)s_hist[b];
        if (c + h >= want) break;
        c += h;
      }
      s_sel = b; s_want = want - c;
    }
    __syncthreads();
    prefix |= ((unsigned)s_sel) << shift;
    want = s_want;
    __syncthreads();
  }
  float thr = ifl(prefix);   /* exact k-th largest value */

  /* gather survivors >= thr (includes value ties -> m may exceed kneed, like the ref) */
  if (tid == 0) s_cnt = 0;
  __syncthreads();
  for (int i = tid; i < count; i += 256){
    float v = s_cand[i];
    if (v >= thr){
      unsigned id = atomicAdd(&s_cnt, 1u);
      if (id < SCAP) s_small[id] = v;
    }
  }
  __syncthreads();
  int m = (int)s_cnt; if (m > SCAP) m = SCAP;
  if (tid >= m) s_small[tid] = -INFINITY;
  __syncthreads();

  /* bitonic sort descending, 256 slots / 256 threads */
  for (int k = 2; k <= SCAP; k <<= 1){
    for (int j = k >> 1; j > 0; j >>= 1){
      int ixj = tid ^ j;
      if (ixj > tid){
        float a = s_small[tid], b = s_small[ixj];
        bool desc = ((tid & k) == 0);
        if (desc ? (a < b) : (a > b)){ s_small[tid] = b; s_small[ixj] = a; }
      }
      __syncthreads();
    }
  }
  float ex_tiny = expf(__fsub_rn(TINYV, M));
  s_e[tid] = (tid < m) ? expf(s_small[tid] - M) : 0.f;
  __syncthreads();

  if (tid == 0){
    double T = (double)(NV - m) * (double)ex_tiny;
    double Z1 = T;
    for (int i = 0; i < m; i++) Z1 += (double)s_e[i];
    double need = (double)__fsub_rn(1.0f, tp) * Z1;
    double suf = T;
    int jstar = 0;
    for (int j = m - 1; j >= 0; j--){
      suf += (double)s_e[j];
      if (suf > need){ jstar = j; break; }
    }
    float thrf = s_small[jstar];
    int nsel = jstar + 1;                     /* POSITION-based kept count (matches ref) */

    /* tie handling at the top-p boundary: stable argsort keeps larger token indices */
    int lo = jstar;
    while (lo > 0 && s_small[lo-1] == thrf) lo--;
    int q = jstar - lo + 1;                   /* kept duplicates of thrf */
    int dcnt = 0;
    for (int i = jstar; i < m && s_small[i] == thrf; i++) dcnt++;
    dcnt += q - 1;                            /* total duplicates among survivors */
    int idx_cut = INT_MIN;
    if (q < dcnt){
      int idxs[64]; int dt = 0;
      for (int i = 0; i < count && dt < 64; i++)
        if (s_cand[i] == thrf) idxs[dt++] = s_cidx[i];
      if (q < dt){
        for (int a = 0; a < q; a++){
          int best = a;
          for (int b2 = a+1; b2 < dt; b2++) if (idxs[b2] > idxs[best]) best = b2;
          int t2 = idxs[a]; idxs[a] = idxs[best]; idxs[best] = t2;
        }
        idx_cut = idxs[q-1];
      }
    }

    double Zsel = 0.0;
    for (int i = 0; i < nsel; i++) Zsel += (double)s_e[i];
    double Z2 = (double)(NV - nsel) * (double)ex_tiny + Zsel;
    float Z2f = (float)Z2;
    float invZ2 = 1.0f / Z2f;
    g_params[row*8+0] = thrf;
    g_params[row*8+1] = M;                    /* M2 == M (M >> TINY always here) */
    g_params[row*8+2] = invZ2;
    g_params[row*8+3] = __fdiv_rn(ex_tiny, Z2f);
    g_params[row*8+4] = __int_as_float(idx_cut);
  }
}

__global__ __launch_bounds__(256) void k_out(
  const float* __restrict__ logits, const float* __restrict__ presence,
  const float* __restrict__ rep, const float* __restrict__ temp,
  float* __restrict__ out, int mode)
{
  int row = blockIdx.y;
  float thrf = g_params[row*8+0], M2 = g_params[row*8+1];
  float invZ2 = g_params[row*8+2], tinyP = g_params[row*8+3];
  int idx_cut = __float_as_int(g_params[row*8+4]);
  float rp = rep[row], pp = presence[row];
  float tv = temp[row]; if (tv < SEPS) tv = 1.f;
  int base = blockIdx.x*CHUNK4;
  const float4* l4 = ((const float4*)(logits + (size_t)row*NV)) + base;
  const unsigned* m4 = ((const unsigned*)(g_mask + (size_t)row*NV)) + base;
  float4* o4 = ((float4*)(out + (size_t)row*NV)) + base;

  for (int i = threadIdx.x; i < CHUNK4; i += 256){
    unsigned mw = m4[i];
    float4 x = compute_x(l4[i], mw, rp, pp, tv);
    int gi = (base + i)*4;
    bool a0 = (x.x > thrf) || (x.x == thrf && gi   >= idx_cut);
    bool a1 = (x.y > thrf) || (x.y == thrf && gi+1 >= idx_cut);
    bool a2 = (x.z > thrf) || (x.z == thrf && gi+2 >= idx_cut);
    bool a3 = (x.w > thrf) || (x.w == thrf && gi+3 >= idx_cut);
    float4 r = make_float4(tinyP, tinyP, tinyP, tinyP);
    if (__any_sync(__activemask(), a0 | a1 | a2 | a3)){
      if (a0) r.x = expf(x.x - M2) * invZ2;
      if (a1) r.y = expf(x.y - M2) * invZ2;
      if (a2) r.z = expf(x.z - M2) * invZ2;
      if (a3) r.w = expf(x.w - M2) * invZ2;
    }
    o4[i] = r;

    if (mode == 1){
      float4 pm, om;
      pm.x = (mw & 0x01u)       ? 1.f : 0.f;
      pm.y = (mw & 0x0100u)     ? 1.f : 0.f;
      pm.z = (mw & 0x010000u)   ? 1.f : 0.f;
      pm.w = (mw & 0x01000000u) ? 1.f : 0.f;
      om.x = (mw & 0x02u)       ? 1.f : 0.f;
      om.y = (mw & 0x0200u)     ? 1.f : 0.f;
      om.z = (mw & 0x020000u)   ? 1.f : 0.f;
      om.w = (mw & 0x02000000u) ? 1.f : 0.f;
      (((float4*)(out + (size_t)NB*NV)) + (size_t)row*N4)[base + i] = pm;
      (((float4*)(out + 2*(size_t)NB*NV)) + (size_t)row*N4)[base + i] = om;
    } else if (mode == 2){
      uchar4 pm, om;
      pm.x = (mw & 0x01u) ? 1 : 0;       pm.y = (mw & 0x0100u) ? 1 : 0;
      pm.z = (mw & 0x010000u) ? 1 : 0;   pm.w = (mw & 0x01000000u) ? 1 : 0;
      om.x = (mw & 0x02u) ? 1 : 0;       om.y = (mw & 0x0200u) ? 1 : 0;
      om.z = (mw & 0x020000u) ? 1 : 0;   om.w = (mw & 0x02000000u) ? 1 : 0;
      unsigned char* bp = (unsigned char*)out + (size_t)NB*NV*4;
      ((uchar4*)(bp + (size_t)row*NV))[base + i] = pm;
      ((uchar4*)(bp + (size_t)NB*NV + (size_t)row*NV))[base + i] = om;
    }
  }
}

extern "C" void kernel_launch(void* const* d_in, const int* in_sizes, int n_in,
                              void* d_out, int out_size) {
  /* size-based input resolution (robust to dict vs alphabetical metadata order) */
  int il = -1, t0 = -1, t1 = -1;
  for (int i = 0; i < n_in; i++){
    if (in_sizes[i] == NB*NV && il < 0) il = i;
    else if (in_sizes[i] > NB){ if (t0 < 0) t0 = i; else t1 = i; }
  }
  int ip, io;
  if (in_sizes[t0] >= in_sizes[t1]){ ip = t0; io = t1; } else { ip = t1; io = t0; }
  int s[6], ns = 0;
  for (int i = 0; i < n_in; i++)
    if (i != il && i != ip && i != io && ns < 6) s[ns++] = i;
  int ipres = (ip < io) ? s[0] : s[1];
  int irep = s[2], itemp = s[3], itopk = s[4], itopp = s[5];

  const float* logits = (const float*)d_in[il];
  const int*   ptoks  = (const int*)d_in[ip];
  const int*   otoks  = (const int*)d_in[io];
  const float* pres   = (const float*)d_in[ipres];
  const float* rep    = (const float*)d_in[irep];
  const float* temp   = (const float*)d_in[itemp];
  const int*   tk     = (const int*)d_in[itopk];
  const float* tp     = (const float*)d_in[itopp];
  float* out = (float*)d_out;

  int PL = in_sizes[ip] / NB;
  int OL = in_sizes[io] / NB;

  long long bv = (long long)NB * NV;
  int mode = 0;
  if ((long long)out_size >= 3*bv) mode = 1;                 /* masks as float */
  else if ((long long)out_size >= bv + bv/2) mode = 2;       /* masks as bytes */

  k_zero<<<512, 256>>>();
  k_scatter<<<(NB*PL + 255)/256, 256>>>(ptoks, PL, 1);
  k_scatter<<<(NB*OL + 255)/256, 256>>>(otoks, OL, 2);
  dim3 grid(BPR, NB);
  k_max<<<grid, 256>>>(logits, pres, rep, temp);
  k_gather<<<grid, 256>>>(logits, pres, rep, temp);
  k_select<<<NB, 256>>>(logits, pres, rep, temp, tk, tp);
  k_out<<<grid, 256>>>(logits, pres, rep, temp, out, mode);
}

// round 6
// speedup vs baseline: 1.1504x; 1.1504x over previous
#include <cuda_runtime.h>
#include <math.h>
#include <limits.h>

#define NB 128
#define NV 128000
#define N4 (NV/4)
#define NW (NV/16)        /* packed mask words per row */
#define BPR 32
#define CHUNK4 (N4/BPR)   /* 1000 float4 per block */
#define TINYV 6.103515625e-05f
#define SEPS 1e-05f
#define CAP 8192
#define SCAP 256

__device__ unsigned g_pk[(size_t)NB*NW];     /* 2 bits/token: bit0 prompt, bit1 output */
__device__ unsigned g_rowmax[NB];
__device__ int g_candcnt[NB];
__device__ float g_cand[NB*CAP];
__device__ int g_cidx[NB*CAP];
__device__ float g_params[NB*8];

__device__ __forceinline__ unsigned ofl(float f){
  unsigned u = __float_as_uint(f);
  return (u & 0x80000000u) ? ~u : (u | 0x80000000u);
}
__device__ __forceinline__ float ifl(unsigned u){
  return __uint_as_float((u & 0x80000000u) ? (u & 0x7FFFFFFFu) : ~u);
}
__device__ __forceinline__ float cutf(float M){
  return M - 0.38f*fabsf(M) - 0.5f;
}
/* bit-exact mirror of reference arithmetic: l/pen (or l*pen), -pp, /temp */
__device__ __forceinline__ float xform(float l, unsigned mb, float rp, float pp, float tv){
  float x = l;
  if (mb){
    x = (l > 0.f) ? __fdiv_rn(l, rp) : __fmul_rn(l, rp);
    if (mb & 2u) x = __fsub_rn(x, pp);
  }
  return __fdiv_rn(x, tv);
}
/* m8: 8 bits = 4 tokens x 2 bits */
__device__ __forceinline__ float4 compute_x(float4 l, unsigned m8, float rp, float pp, float tv){
  float4 r;
  r.x = xform(l.x, (m8     ) & 3u, rp, pp, tv);
  r.y = xform(l.y, (m8 >> 2) & 3u, rp, pp, tv);
  r.z = xform(l.z, (m8 >> 4) & 3u, rp, pp, tv);
  r.w = xform(l.w, (m8 >> 6) & 3u, rp, pp, tv);
  return r;
}
/* mask byte for float4 index i within a row (gi = i*4, gi%16 in {0,4,8,12}) */
__device__ __forceinline__ unsigned mask8(const unsigned* __restrict__ pk, int i){
  unsigned w = pk[i >> 2];
  return (w >> ((i & 3) << 3)) & 0xFFu;
}

__global__ void k_init(){
  size_t i0 = (size_t)blockIdx.x*blockDim.x + threadIdx.x;
  size_t n = (size_t)NB*NW;
  for (size_t i = i0; i < n; i += (size_t)gridDim.x*blockDim.x) g_pk[i] = 0u;
  if (i0 < NB){ g_rowmax[i0] = 0u; g_candcnt[i0] = 0; }
}

__global__ void k_scatter(const int* __restrict__ toks, int L, unsigned bit){
  int i = blockIdx.x*blockDim.x + threadIdx.x;
  if (i >= NB*L) return;
  int row = i / L;
  int t = toks[i];
  if (t >= 0 && t < NV)
    atomicOr(&g_pk[(size_t)row*NW + (t >> 4)], bit << ((t & 15)*2));
}

/* fused: chunk max (+ global row max) and superset candidate collection */
__global__ __launch_bounds__(256) void k_pass1(
  const float* __restrict__ logits, const float* __restrict__ presence,
  const float* __restrict__ rep, const float* __restrict__ temp)
{
  __shared__ float s_red[8];
  __shared__ float s_bmax;
  int row = blockIdx.y;
  float rp = rep[row], pp = presence[row];
  float tv = temp[row]; if (tv < SEPS) tv = 1.f;
  int base = blockIdx.x*CHUNK4;
  const float4* l4 = ((const float4*)(logits + (size_t)row*NV)) + base;
  const unsigned* pk = g_pk + (size_t)row*NW + base;   /* base float4 -> base words offset: base/4 words */
  /* careful: one word covers 4 float4's; word offset for float4 index (base+i) is (base+i)>>2 */
  const unsigned* pkrow = g_pk + (size_t)row*NW;

  float mymax = -INFINITY;
  for (int i = threadIdx.x; i < CHUNK4; i += 256){
    float4 x = compute_x(l4[i], mask8(pkrow, base + i), rp, pp, tv);
    mymax = fmaxf(fmaxf(mymax, fmaxf(x.x, x.y)), fmaxf(x.z, x.w));
  }
  #pragma unroll
  for (int o = 16; o > 0; o >>= 1) mymax = fmaxf(mymax, __shfl_xor_sync(0xFFFFFFFFu, mymax, o));
  if ((threadIdx.x & 31) == 0) s_red[threadIdx.x >> 5] = mymax;
  __syncthreads();
  if (threadIdx.x == 0){
    float v = s_red[0];
    #pragma unroll
    for (int w = 1; w < 8; w++) v = fmaxf(v, s_red[w]);
    s_bmax = v;
    atomicMax(&g_rowmax[row], ofl(v));
  }
  __syncthreads();
  float cut = cutf(s_bmax);   /* chunk-local cut <= global cut -> superset */

  for (int i = threadIdx.x; i < CHUNK4; i += 256){
    float4 x = compute_x(l4[i], mask8(pkrow, base + i), rp, pp, tv);  /* L1 hit */
    float v[4] = {x.x, x.y, x.z, x.w};
    #pragma unroll
    for (int j = 0; j < 4; j++){
      if (v[j] >= cut){
        int p = atomicAdd(&g_candcnt[row], 1);
        if (p < CAP){ g_cand[row*CAP + p] = v[j]; g_cidx[row*CAP + p] = (base + i)*4 + j; }
      }
    }
  }
  (void)pk;
}

__global__ __launch_bounds__(256) void k_select(
  const float* __restrict__ logits, const float* __restrict__ presence,
  const float* __restrict__ rep, const float* __restrict__ temp,
  const int* __restrict__ topk, const float* __restrict__ topp)
{
  __shared__ unsigned s_hist[256];
  __shared__ float s_small[SCAP];
  __shared__ float s_e[SCAP];
  __shared__ double s_d[SCAP];
  __shared__ unsigned s_cnt;
  __shared__ int s_sel, s_want, s_jstar;

  int row = blockIdx.x, tid = threadIdx.x;
  float M = ifl(g_rowmax[row]);
  int kneed = topk[row]; if (kneed < 1) kneed = 1; if (kneed > NV) kneed = NV;
  float tp = topp[row];
  int count = g_candcnt[row];
  float* cand = g_cand + row*CAP;
  int* cidx = g_cidx + row*CAP;

  if (!(count >= kneed && count <= CAP)){
    /* fallback: bracketed global-cut search (cold path) */
    float rp = rep[row], pp = presence[row];
    float tv = temp[row]; if (tv < SEPS) tv = 1.f;
    const float4* l4 = (const float4*)(logits + (size_t)row*NV);
    const unsigned* pkrow = g_pk + (size_t)row*NW;
    float delta = 0.38f*fabsf(M) + 0.5f;
    float dlo = 0.f, dhi = -1.f;
    if (count < kneed){ dlo = delta; delta *= 2.f; }
    else              { dhi = delta; delta *= 0.5f; }
    for (int it = 0; it < 64; it++){
      float c2 = M - delta;
      if (tid == 0) s_cnt = 0;
      __syncthreads();
      for (int i = tid; i < N4; i += 256){
        float4 x = compute_x(l4[i], mask8(pkrow, i), rp, pp, tv);
        float v[4] = {x.x, x.y, x.z, x.w};
        #pragma unroll
        for (int j = 0; j < 4; j++){
          if (v[j] >= c2){
            unsigned id = atomicAdd(&s_cnt, 1u);
            if (id < CAP){ cand[id] = v[j]; cidx[id] = i*4 + j; }
          }
        }
      }
      __syncthreads();
      count = (int)s_cnt;
      __syncthreads();
      if (count >= kneed && count <= CAP) break;
      if (count < kneed){ dlo = delta; delta = (dhi > 0.f) ? 0.5f*(delta + dhi) : delta*2.f; }
      else              { dhi = delta; delta = 0.5f*(dlo + delta); }
    }
    if (count > CAP) count = CAP;
    if (count < kneed) kneed = count;
  }
  __syncthreads();

  /* radix-select k-th largest value (streamed from L2-resident global) */
  unsigned prefix = 0; int want = kneed;
  for (int shift = 24; shift >= 0; shift -= 8){
    s_hist[tid] = 0;
    __syncthreads();
    unsigned himask = (shift == 24) ? 0u : (0xFFFFFFFFu << (shift + 8));
    for (int i = tid; i < count; i += 256){
      unsigned ou = ofl(cand[i]);
      if ((ou & himask) == prefix) atomicAdd(&s_hist[(ou >> shift) & 255u], 1u);
    }
    __syncthreads();
    if (tid == 0){
      int c = 0, b = 255;
      for (; b > 0; b--){
        int h = (int)s_hist[b];
        if (c + h >= want) break;
        c += h;
      }
      s_sel = b; s_want = want - c;
    }
    __syncthreads();
    prefix |= ((unsigned)s_sel) << shift;
    want = s_want;
    __syncthreads();
  }
  float thr = ifl(prefix);   /* exact k-th largest value */

  /* gather survivors >= thr (value ties included, like the ref) */
  if (tid == 0) s_cnt = 0;
  __syncthreads();
  for (int i = tid; i < count; i += 256){
    float v = cand[i];
    if (v >= thr){
      unsigned id = atomicAdd(&s_cnt, 1u);
      if (id < SCAP) s_small[id] = v;
    }
  }
  __syncthreads();
  int m = (int)s_cnt; if (m > SCAP) m = SCAP;
  if (tid >= m) s_small[tid] = -INFINITY;
  __syncthreads();

  /* bitonic sort descending, 256 slots / 256 threads */
  for (int k = 2; k <= SCAP; k <<= 1){
    for (int j = k >> 1; j > 0; j >>= 1){
      int ixj = tid ^ j;
      if (ixj > tid){
        float a = s_small[tid], b = s_small[ixj];
        bool desc = ((tid & k) == 0);
        if (desc ? (a < b) : (a > b)){ s_small[tid] = b; s_small[ixj] = a; }
      }
      __syncthreads();
    }
  }
  float ex_tiny = expf(__fsub_rn(TINYV, M));
  s_e[tid] = (tid < m) ? expf(s_small[tid] - M) : 0.f;
  __syncthreads();

  /* parallel suffix sums: s_d[j] = sum_{i>=j} e[i] */
  s_d[tid] = (double)s_e[tid];
  __syncthreads();
  #pragma unroll
  for (int off = 1; off < SCAP; off <<= 1){
    double add = (tid + off < SCAP) ? s_d[tid + off] : 0.0;
    __syncthreads();
    s_d[tid] += add;
    __syncthreads();
  }
  double T = (double)(NV - m) * (double)ex_tiny;
  double Z1 = T + s_d[0];
  double need = (double)__fsub_rn(1.0f, tp) * Z1;
  if (tid == 0) s_jstar = 0;
  __syncthreads();
  if (tid < m && (T + s_d[tid]) > need) atomicMax(&s_jstar, tid);
  __syncthreads();

  if (tid == 0){
    int jstar = s_jstar;
    float thrf = s_small[jstar];
    int nsel = jstar + 1;                     /* position-based kept count */

    /* tie handling at the top-p boundary (stable argsort keeps larger token idx) */
    int lo = jstar;
    while (lo > 0 && s_small[lo-1] == thrf) lo--;
    int q = jstar - lo + 1;
    int dcnt = 0;
    for (int i = jstar; i < m && s_small[i] == thrf; i++) dcnt++;
    dcnt += q - 1;
    int idx_cut = INT_MIN;
    if (q < dcnt){
      int idxs[64]; int dt = 0;
      for (int i = 0; i < count && dt < 64; i++)
        if (cand[i] == thrf) idxs[dt++] = cidx[i];
      if (q < dt){
        for (int a = 0; a < q; a++){
          int best = a;
          for (int b2 = a+1; b2 < dt; b2++) if (idxs[b2] > idxs[best]) best = b2;
          int t2 = idxs[a]; idxs[a] = idxs[best]; idxs[best] = t2;
        }
        idx_cut = idxs[q-1];
      }
    }

    double Zsel = s_d[0] - ((jstar+1 < SCAP) ? s_d[jstar+1] : 0.0);
    double Z2 = (double)(NV - nsel) * (double)ex_tiny + Zsel;
    float Z2f = (float)Z2;
    float invZ2 = 1.0f / Z2f;
    g_params[row*8+0] = thrf;
    g_params[row*8+1] = M;
    g_params[row*8+2] = invZ2;
    g_params[row*8+3] = __fdiv_rn(ex_tiny, Z2f);
    g_params[row*8+4] = __int_as_float(idx_cut);
  }
}

__global__ __launch_bounds__(256) void k_out(
  const float* __restrict__ logits, const float* __restrict__ presence,
  const float* __restrict__ rep, const float* __restrict__ temp,
  float* __restrict__ out, int mode)
{
  int row = blockIdx.y;
  float thrf = g_params[row*8+0], M2 = g_params[row*8+1];
  float invZ2 = g_params[row*8+2], tinyP = g_params[row*8+3];
  int idx_cut = __float_as_int(g_params[row*8+4]);
  float rp = rep[row], pp = presence[row];
  float tv = temp[row]; if (tv < SEPS) tv = 1.f;
  int base = blockIdx.x*CHUNK4;
  const float4* l4 = ((const float4*)(logits + (size_t)row*NV)) + base;
  const unsigned* pkrow = g_pk + (size_t)row*NW;
  float4* o4 = ((float4*)(out + (size_t)row*NV)) + base;

  for (int i = threadIdx.x; i < CHUNK4; i += 256){
    unsigned m8 = mask8(pkrow, base + i);
    float4 x = compute_x(l4[i], m8, rp, pp, tv);
    int gi = (base + i)*4;
    bool a0 = (x.x > thrf) || (x.x == thrf && gi   >= idx_cut);
    bool a1 = (x.y > thrf) || (x.y == thrf && gi+1 >= idx_cut);
    bool a2 = (x.z > thrf) || (x.z == thrf && gi+2 >= idx_cut);
    bool a3 = (x.w > thrf) || (x.w == thrf && gi+3 >= idx_cut);
    float4 r = make_float4(tinyP, tinyP, tinyP, tinyP);
    if (__any_sync(__activemask(), a0 | a1 | a2 | a3)){
      if (a0) r.x = expf(x.x - M2) * invZ2;
      if (a1) r.y = expf(x.y - M2) * invZ2;
      if (a2) r.z = expf(x.z - M2) * invZ2;
      if (a3) r.w = expf(x.w - M2) * invZ2;
    }
    o4[i] = r;

    if (mode == 1){
      float4 pm, om;
      pm.x = (m8 & 0x01u) ? 1.f : 0.f;  om.x = (m8 & 0x02u) ? 1.f : 0.f;
      pm.y = (m8 & 0x04u) ? 1.f : 0.f;  om.y = (m8 & 0x08u) ? 1.f : 0.f;
      pm.z = (m8 & 0x10u) ? 1.f : 0.f;  om.z = (m8 & 0x20u) ? 1.f : 0.f;
      pm.w = (m8 & 0x40u) ? 1.f : 0.f;  om.w = (m8 & 0x80u) ? 1.f : 0.f;
      (((float4*)(out + (size_t)NB*NV)) + (size_t)row*N4)[base + i] = pm;
      (((float4*)(out + 2*(size_t)NB*NV)) + (size_t)row*N4)[base + i] = om;
    } else if (mode == 2){
      uchar4 pm, om;
      pm.x = (m8 & 0x01u) ? 1 : 0;  om.x = (m8 & 0x02u) ? 1 : 0;
      pm.y = (m8 & 0x04u) ? 1 : 0;  om.y = (m8 & 0x08u) ? 1 : 0;
      pm.z = (m8 & 0x10u) ? 1 : 0;  om.z = (m8 & 0x20u) ? 1 : 0;
      pm.w = (m8 & 0x40u) ? 1 : 0;  om.w = (m8 & 0x80u) ? 1 : 0;
      unsigned char* bp = (unsigned char*)out + (size_t)NB*NV*4;
      ((uchar4*)(bp + (size_t)row*NV))[base + i] = pm;
      ((uchar4*)(bp + (size_t)NB*NV + (size_t)row*NV))[base + i] = om;
    }
  }
}

extern "C" void kernel_launch(void* const* d_in, const int* in_sizes, int n_in,
                              void* d_out, int out_size) {
  /* size-based input resolution (robust to dict vs alphabetical metadata order) */
  int il = -1, t0 = -1, t1 = -1;
  for (int i = 0; i < n_in; i++){
    if (in_sizes[i] == NB*NV && il < 0) il = i;
    else if (in_sizes[i] > NB){ if (t0 < 0) t0 = i; else t1 = i; }
  }
  int ip, io;
  if (in_sizes[t0] >= in_sizes[t1]){ ip = t0; io = t1; } else { ip = t1; io = t0; }
  int s[6], ns = 0;
  for (int i = 0; i < n_in; i++)
    if (i != il && i != ip && i != io && ns < 6) s[ns++] = i;
  int ipres = (ip < io) ? s[0] : s[1];
  int irep = s[2], itemp = s[3], itopk = s[4], itopp = s[5];

  const float* logits = (const float*)d_in[il];
  const int*   ptoks  = (const int*)d_in[ip];
  const int*   otoks  = (const int*)d_in[io];
  const float* pres   = (const float*)d_in[ipres];
  const float* rep    = (const float*)d_in[irep];
  const float* temp   = (const float*)d_in[itemp];
  const int*   tk     = (const int*)d_in[itopk];
  const float* tp     = (const float*)d_in[itopp];
  float* out = (float*)d_out;

  int PL = in_sizes[ip] / NB;
  int OL = in_sizes[io] / NB;

  long long bv = (long long)NB * NV;
  int mode = 0;
  if ((long long)out_size >= 3*bv) mode = 1;                 /* masks as float */
  else if ((long long)out_size >= bv + bv/2) mode = 2;       /* masks as bytes */

  k_init<<<512, 256>>>();
  k_scatter<<<(NB*PL + 255)/256, 256>>>(ptoks, PL, 1u);
  k_scatter<<<(NB*OL + 255)/256, 256>>>(otoks, OL, 2u);
  dim3 grid(BPR, NB);
  k_pass1<<<grid, 256>>>(logits, pres, rep, temp);
  k_select<<<NB, 256>>>(logits, pres, rep, temp, tk, tp);
  k_out<<<grid, 256>>>(logits, pres, rep, temp, out, mode);
}

// round 7
// speedup vs baseline: 1.5986x; 1.3896x over previous
#include <cuda_runtime.h>
#include <math.h>
#include <limits.h>

#define NB 128
#define NV 128000
#define N4 (NV/4)
#define NW (NV/16)        /* packed mask words per row */
#define BPR 32
#define CHUNK4 (N4/BPR)   /* 1000 float4 per block */
#define TINYV 6.103515625e-05f
#define SEPS 1e-05f
#define CAP 8192
#define SCAP 256
#define SBUF 2048

__device__ unsigned g_pk[(size_t)NB*NW];     /* 2 bits/token: bit0 prompt, bit1 output */
__device__ unsigned g_rowmax[NB];
__device__ int g_candcnt[NB];
__device__ float g_cand[NB*CAP];
__device__ int g_cidx[NB*CAP];
__device__ float g_params[NB*8];

__device__ __forceinline__ unsigned ofl(float f){
  unsigned u = __float_as_uint(f);
  return (u & 0x80000000u) ? ~u : (u | 0x80000000u);
}
__device__ __forceinline__ float ifl(unsigned u){
  return __uint_as_float((u & 0x80000000u) ? (u & 0x7FFFFFFFu) : ~u);
}
__device__ __forceinline__ float cutf(float M){
  return M - 0.38f*fabsf(M) - 0.5f;
}
/* bit-exact mirror of reference arithmetic: l/pen (or l*pen), -pp, /temp */
__device__ __forceinline__ float xform(float l, unsigned mb, float rp, float pp, float tv){
  float x = l;
  if (mb){
    x = (l > 0.f) ? __fdiv_rn(l, rp) : __fmul_rn(l, rp);
    if (mb & 2u) x = __fsub_rn(x, pp);
  }
  return __fdiv_rn(x, tv);
}
__device__ __forceinline__ float4 compute_x(float4 l, unsigned m8, float rp, float pp, float tv){
  float4 r;
  r.x = xform(l.x, (m8     ) & 3u, rp, pp, tv);
  r.y = xform(l.y, (m8 >> 2) & 3u, rp, pp, tv);
  r.z = xform(l.z, (m8 >> 4) & 3u, rp, pp, tv);
  r.w = xform(l.w, (m8 >> 6) & 3u, rp, pp, tv);
  return r;
}
__device__ __forceinline__ unsigned mask8(const unsigned* __restrict__ pk, int i){
  unsigned w = pk[i >> 2];
  return (w >> ((i & 3) << 3)) & 0xFFu;
}

__global__ void k_init(){
  size_t i0 = (size_t)blockIdx.x*blockDim.x + threadIdx.x;
  size_t n = (size_t)NB*NW;
  for (size_t i = i0; i < n; i += (size_t)gridDim.x*blockDim.x) g_pk[i] = 0u;
  if (i0 < NB){ g_rowmax[i0] = 0u; g_candcnt[i0] = 0; }
}

__global__ void k_scatter(const int* __restrict__ toks, int L, unsigned bit){
  int i = blockIdx.x*blockDim.x + threadIdx.x;
  if (i >= NB*L) return;
  int row = i / L;
  int t = toks[i];
  if (t >= 0 && t < NV)
    atomicOr(&g_pk[(size_t)row*NW + (t >> 4)], bit << ((t & 15)*2));
}

/* fused: chunk max (+ global row max) and superset candidate collection,
   with block-private candidate staging (one global atomic per block) */
__global__ __launch_bounds__(256) void k_pass1(
  const float* __restrict__ logits, const float* __restrict__ presence,
  const float* __restrict__ rep, const float* __restrict__ temp)
{
  __shared__ float s_red[8];
  __shared__ float s_bmax;
  __shared__ float sb_v[SBUF];
  __shared__ int   sb_i[SBUF];
  __shared__ unsigned sb_n;
  __shared__ unsigned sb_base;

  int row = blockIdx.y;
  float rp = rep[row], pp = presence[row];
  float tv = temp[row]; if (tv < SEPS) tv = 1.f;
  int base = blockIdx.x*CHUNK4;
  const float4* l4 = ((const float4*)(logits + (size_t)row*NV)) + base;
  const unsigned* pkrow = g_pk + (size_t)row*NW;

  if (threadIdx.x == 0) sb_n = 0;

  float mymax = -INFINITY;
  for (int i = threadIdx.x; i < CHUNK4; i += 256){
    float4 x = compute_x(l4[i], mask8(pkrow, base + i), rp, pp, tv);
    mymax = fmaxf(fmaxf(mymax, fmaxf(x.x, x.y)), fmaxf(x.z, x.w));
  }
  #pragma unroll
  for (int o = 16; o > 0; o >>= 1) mymax = fmaxf(mymax, __shfl_xor_sync(0xFFFFFFFFu, mymax, o));
  if ((threadIdx.x & 31) == 0) s_red[threadIdx.x >> 5] = mymax;
  __syncthreads();
  if (threadIdx.x == 0){
    float v = s_red[0];
    #pragma unroll
    for (int w = 1; w < 8; w++) v = fmaxf(v, s_red[w]);
    s_bmax = v;
    atomicMax(&g_rowmax[row], ofl(v));
  }
  __syncthreads();
  float cut = cutf(s_bmax);   /* chunk-local cut <= global cut -> superset */

  for (int i = threadIdx.x; i < CHUNK4; i += 256){
    float4 x = compute_x(l4[i], mask8(pkrow, base + i), rp, pp, tv);  /* L1/L2 hit */
    float v[4] = {x.x, x.y, x.z, x.w};
    #pragma unroll
    for (int j = 0; j < 4; j++){
      if (v[j] >= cut){
        unsigned id = atomicAdd(&sb_n, 1u);          /* shared atomic: cheap */
        if (id < SBUF){ sb_v[id] = v[j]; sb_i[id] = (base + i)*4 + j; }
        else {                                        /* overflow: rare direct path */
          int p = atomicAdd(&g_candcnt[row], 1);
          if (p < CAP){ g_cand[row*CAP + p] = v[j]; g_cidx[row*CAP + p] = (base + i)*4 + j; }
        }
      }
    }
  }
  __syncthreads();
  unsigned n = sb_n; if (n > SBUF) n = SBUF;
  if (threadIdx.x == 0) sb_base = (unsigned)atomicAdd(&g_candcnt[row], (int)n);
  __syncthreads();
  unsigned b0 = sb_base;
  for (unsigned i = threadIdx.x; i < n; i += 256){
    unsigned p = b0 + i;
    if (p < CAP){ g_cand[row*CAP + p] = sb_v[i]; g_cidx[row*CAP + p] = sb_i[i]; }
  }
}

__global__ __launch_bounds__(256) void k_select(
  const float* __restrict__ logits, const float* __restrict__ presence,
  const float* __restrict__ rep, const float* __restrict__ temp,
  const int* __restrict__ topk, const float* __restrict__ topp)
{
  __shared__ unsigned s_hist[256];
  __shared__ float s_small[SCAP];
  __shared__ float s_e[SCAP];
  __shared__ double s_d[SCAP];
  __shared__ unsigned s_cnt;
  __shared__ int s_sel, s_want, s_jstar;

  int row = blockIdx.x, tid = threadIdx.x;
  float M = ifl(g_rowmax[row]);
  int kneed = topk[row]; if (kneed < 1) kneed = 1; if (kneed > NV) kneed = NV;
  float tp = topp[row];
  int count = g_candcnt[row];
  float* cand = g_cand + row*CAP;
  int* cidx = g_cidx + row*CAP;

  if (!(count >= kneed && count <= CAP)){
    /* fallback: bracketed global-cut search (cold path) */
    float rp = rep[row], pp = presence[row];
    float tv = temp[row]; if (tv < SEPS) tv = 1.f;
    const float4* l4 = (const float4*)(logits + (size_t)row*NV);
    const unsigned* pkrow = g_pk + (size_t)row*NW;
    float delta = 0.38f*fabsf(M) + 0.5f;
    float dlo = 0.f, dhi = -1.f;
    if (count < kneed){ dlo = delta; delta *= 2.f; }
    else              { dhi = delta; delta *= 0.5f; }
    for (int it = 0; it < 64; it++){
      float c2 = M - delta;
      if (tid == 0) s_cnt = 0;
      __syncthreads();
      for (int i = tid; i < N4; i += 256){
        float4 x = compute_x(l4[i], mask8(pkrow, i), rp, pp, tv);
        float v[4] = {x.x, x.y, x.z, x.w};
        #pragma unroll
        for (int j = 0; j < 4; j++){
          if (v[j] >= c2){
            unsigned id = atomicAdd(&s_cnt, 1u);
            if (id < CAP){ cand[id] = v[j]; cidx[id] = i*4 + j; }
          }
        }
      }
      __syncthreads();
      count = (int)s_cnt;
      __syncthreads();
      if (count >= kneed && count <= CAP) break;
      if (count < kneed){ dlo = delta; delta = (dhi > 0.f) ? 0.5f*(delta + dhi) : delta*2.f; }
      else              { dhi = delta; delta = 0.5f*(dlo + delta); }
    }
    if (count > CAP) count = CAP;
    if (count < kneed) kneed = count;
  }
  __syncthreads();

  /* radix-select k-th largest value (streamed from L2-resident global) */
  unsigned prefix = 0; int want = kneed;
  for (int shift = 24; shift >= 0; shift -= 8){
    s_hist[tid] = 0;
    __syncthreads();
    unsigned himask = (shift == 24) ? 0u : (0xFFFFFFFFu << (shift + 8));
    for (int i = tid; i < count; i += 256){
      unsigned ou = ofl(cand[i]);
      if ((ou & himask) == prefix) atomicAdd(&s_hist[(ou >> shift) & 255u], 1u);
    }
    __syncthreads();
    if (tid == 0){
      int c = 0, b = 255;
      for (; b > 0; b--){
        int h = (int)s_hist[b];
        if (c + h >= want) break;
        c += h;
      }
      s_sel = b; s_want = want - c;
    }
    __syncthreads();
    prefix |= ((unsigned)s_sel) << shift;
    want = s_want;
    __syncthreads();
  }
  float thr = ifl(prefix);   /* exact k-th largest value */

  /* gather survivors >= thr (value ties included, like the ref) */
  if (tid == 0) s_cnt = 0;
  __syncthreads();
  for (int i = tid; i < count; i += 256){
    float v = cand[i];
    if (v >= thr){
      unsigned id = atomicAdd(&s_cnt, 1u);
      if (id < SCAP) s_small[id] = v;
    }
  }
  __syncthreads();
  int m = (int)s_cnt; if (m > SCAP) m = SCAP;
  if (tid >= m) s_small[tid] = -INFINITY;
  __syncthreads();

  /* bitonic sort descending */
  for (int k = 2; k <= SCAP; k <<= 1){
    for (int j = k >> 1; j > 0; j >>= 1){
      int ixj = tid ^ j;
      if (ixj > tid){
        float a = s_small[tid], b = s_small[ixj];
        bool desc = ((tid & k) == 0);
        if (desc ? (a < b) : (a > b)){ s_small[tid] = b; s_small[ixj] = a; }
      }
      __syncthreads();
    }
  }
  float ex_tiny = expf(__fsub_rn(TINYV, M));
  s_e[tid] = (tid < m) ? expf(s_small[tid] - M) : 0.f;
  __syncthreads();

  /* parallel suffix sums: s_d[j] = sum_{i>=j} e[i] */
  s_d[tid] = (double)s_e[tid];
  __syncthreads();
  #pragma unroll
  for (int off = 1; off < SCAP; off <<= 1){
    double add = (tid + off < SCAP) ? s_d[tid + off] : 0.0;
    __syncthreads();
    s_d[tid] += add;
    __syncthreads();
  }
  double T = (double)(NV - m) * (double)ex_tiny;
  double Z1 = T + s_d[0];
  double need = (double)__fsub_rn(1.0f, tp) * Z1;
  if (tid == 0) s_jstar = 0;
  __syncthreads();
  if (tid < m && (T + s_d[tid]) > need) atomicMax(&s_jstar, tid);
  __syncthreads();

  if (tid == 0){
    int jstar = s_jstar;
    float thrf = s_small[jstar];
    int nsel = jstar + 1;                     /* position-based kept count */

    /* tie handling at top-p boundary (stable argsort keeps larger token idx) */
    int lo = jstar;
    while (lo > 0 && s_small[lo-1] == thrf) lo--;
    int q = jstar - lo + 1;
    int dcnt = 0;
    for (int i = jstar; i < m && s_small[i] == thrf; i++) dcnt++;
    dcnt += q - 1;
    int idx_cut = INT_MIN;
    if (q < dcnt){
      int idxs[64]; int dt = 0;
      for (int i = 0; i < count && dt < 64; i++)
        if (cand[i] == thrf) idxs[dt++] = cidx[i];
      if (q < dt){
        for (int a = 0; a < q; a++){
          int best = a;
          for (int b2 = a+1; b2 < dt; b2++) if (idxs[b2] > idxs[best]) best = b2;
          int t2 = idxs[a]; idxs[a] = idxs[best]; idxs[best] = t2;
        }
        idx_cut = idxs[q-1];
      }
    }

    double Zsel = s_d[0] - ((jstar+1 < SCAP) ? s_d[jstar+1] : 0.0);
    double Z2 = (double)(NV - nsel) * (double)ex_tiny + Zsel;
    float Z2f = (float)Z2;
    float invZ2 = 1.0f / Z2f;
    g_params[row*8+0] = thrf;
    g_params[row*8+1] = M;
    g_params[row*8+2] = invZ2;
    g_params[row*8+3] = __fdiv_rn(ex_tiny, Z2f);
    g_params[row*8+4] = __int_as_float(idx_cut);
  }
}

__global__ __launch_bounds__(256) void k_out(
  const float* __restrict__ logits, const float* __restrict__ presence,
  const float* __restrict__ rep, const float* __restrict__ temp,
  float* __restrict__ out, int mode)
{
  int row = blockIdx.y;
  float thrf = g_params[row*8+0], M2 = g_params[row*8+1];
  float invZ2 = g_params[row*8+2], tinyP = g_params[row*8+3];
  int idx_cut = __float_as_int(g_params[row*8+4]);
  float rp = rep[row], pp = presence[row];
  float tv = temp[row]; if (tv < SEPS) tv = 1.f;
  int base = blockIdx.x*CHUNK4;
  const float4* l4 = ((const float4*)(logits + (size_t)row*NV)) + base;
  const unsigned* pkrow = g_pk + (size_t)row*NW;
  float4* o4 = ((float4*)(out + (size_t)row*NV)) + base;

  for (int i = threadIdx.x; i < CHUNK4; i += 256){
    unsigned m8 = mask8(pkrow, base + i);
    float4 x = compute_x(l4[i], m8, rp, pp, tv);
    int gi = (base + i)*4;
    bool a0 = (x.x > thrf) || (x.x == thrf && gi   >= idx_cut);
    bool a1 = (x.y > thrf) || (x.y == thrf && gi+1 >= idx_cut);
    bool a2 = (x.z > thrf) || (x.z == thrf && gi+2 >= idx_cut);
    bool a3 = (x.w > thrf) || (x.w == thrf && gi+3 >= idx_cut);
    float4 r = make_float4(tinyP, tinyP, tinyP, tinyP);
    if (__any_sync(__activemask(), a0 | a1 | a2 | a3)){
      if (a0) r.x = expf(x.x - M2) * invZ2;
      if (a1) r.y = expf(x.y - M2) * invZ2;
      if (a2) r.z = expf(x.z - M2) * invZ2;
      if (a3) r.w = expf(x.w - M2) * invZ2;
    }
    o4[i] = r;

    if (mode == 1){
      float4 pm, om;
      pm.x = (m8 & 0x01u) ? 1.f : 0.f;  om.x = (m8 & 0x02u) ? 1.f : 0.f;
      pm.y = (m8 & 0x04u) ? 1.f : 0.f;  om.y = (m8 & 0x08u) ? 1.f : 0.f;
      pm.z = (m8 & 0x10u) ? 1.f : 0.f;  om.z = (m8 & 0x20u) ? 1.f : 0.f;
      pm.w = (m8 & 0x40u) ? 1.f : 0.f;  om.w = (m8 & 0x80u) ? 1.f : 0.f;
      (((float4*)(out + (size_t)NB*NV)) + (size_t)row*N4)[base + i] = pm;
      (((float4*)(out + 2*(size_t)NB*NV)) + (size_t)row*N4)[base + i] = om;
    } else if (mode == 2){
      uchar4 pm, om;
      pm.x = (m8 & 0x01u) ? 1 : 0;  om.x = (m8 & 0x02u) ? 1 : 0;
      pm.y = (m8 & 0x04u) ? 1 : 0;  om.y = (m8 & 0x08u) ? 1 : 0;
      pm.z = (m8 & 0x10u) ? 1 : 0;  om.z = (m8 & 0x20u) ? 1 : 0;
      pm.w = (m8 & 0x40u) ? 1 : 0;  om.w = (m8 & 0x80u) ? 1 : 0;
      unsigned char* bp = (unsigned char*)out + (size_t)NB*NV*4;
      ((uchar4*)(bp + (size_t)row*NV))[base + i] = pm;
      ((uchar4*)(bp + (size_t)NB*NV + (size_t)row*NV))[base + i] = om;
    }
  }
}

extern "C" void kernel_launch(void* const* d_in, const int* in_sizes, int n_in,
                              void* d_out, int out_size) {
  /* size-based input resolution (robust to dict vs alphabetical metadata order) */
  int il = -1, t0 = -1, t1 = -1;
  for (int i = 0; i < n_in; i++){
    if (in_sizes[i] == NB*NV && il < 0) il = i;
    else if (in_sizes[i] > NB){ if (t0 < 0) t0 = i; else t1 = i; }
  }
  int ip, io;
  if (in_sizes[t0] >= in_sizes[t1]){ ip = t0; io = t1; } else { ip = t1; io = t0; }
  int s[6], ns = 0;
  for (int i = 0; i < n_in; i++)
    if (i != il && i != ip && i != io && ns < 6) s[ns++] = i;
  int ipres = (ip < io) ? s[0] : s[1];
  int irep = s[2], itemp = s[3], itopk = s[4], itopp = s[5];

  const float* logits = (const float*)d_in[il];
  const int*   ptoks  = (const int*)d_in[ip];
  const int*   otoks  = (const int*)d_in[io];
  const float* pres   = (const float*)d_in[ipres];
  const float* rep    = (const float*)d_in[irep];
  const float* temp   = (const float*)d_in[itemp];
  const int*   tk     = (const int*)d_in[itopk];
  const float* tp     = (const float*)d_in[itopp];
  float* out = (float*)d_out;

  int PL = in_sizes[ip] / NB;
  int OL = in_sizes[io] / NB;

  long long bv = (long long)NB * NV;
  int mode = 0;
  if ((long long)out_size >= 3*bv) mode = 1;                 /* masks as float */
  else if ((long long)out_size >= bv + bv/2) mode = 2;       /* masks as bytes */

  k_init<<<512, 256>>>();
  k_scatter<<<(NB*PL + 255)/256, 256>>>(ptoks, PL, 1u);
  k_scatter<<<(NB*OL + 255)/256, 256>>>(otoks, OL, 2u);
  dim3 grid(BPR, NB);
  k_pass1<<<grid, 256>>>(logits, pres, rep, temp);
  k_select<<<NB, 256>>>(logits, pres, rep, temp, tk, tp);
  k_out<<<grid, 256>>>(logits, pres, rep, temp, out, mode);
}

// round 8
// speedup vs baseline: 1.6465x; 1.0299x over previous
#include <cuda_runtime.h>
#include <math.h>
#include <limits.h>

#define NB 128
#define NV 128000
#define N4 (NV/4)
#define NW (NV/16)        /* packed mask words per row */
#define BPR 32
#define CHUNK4 (N4/BPR)   /* 1000 float4 per block */
#define TINYV 6.103515625e-05f
#define SEPS 1e-05f
#define CAP 8192
#define SCAP 256
#define SBUF 2048
#define CUTMARG 0.02f

__device__ unsigned g_pk[(size_t)NB*NW];     /* 2 bits/token: bit0 prompt, bit1 output */
__device__ int g_candcnt[NB];
__device__ float g_cand[NB*CAP];             /* EXACT candidate values */
__device__ int g_cidx[NB*CAP];
__device__ float g_params[NB*8];

__device__ __forceinline__ unsigned ofl(float f){
  unsigned u = __float_as_uint(f);
  return (u & 0x80000000u) ? ~u : (u | 0x80000000u);
}
__device__ __forceinline__ float ifl(unsigned u){
  return __uint_as_float((u & 0x80000000u) ? (u & 0x7FFFFFFFu) : ~u);
}
__device__ __forceinline__ float cutf(float M){
  return M - 0.38f*fabsf(M) - 0.5f;
}
/* EXACT mirror of reference arithmetic: l/pen (or l*pen), -pp, /temp */
__device__ __forceinline__ float xform(float l, unsigned mb, float rp, float pp, float tv){
  float x = l;
  if (mb){
    x = (l > 0.f) ? __fdiv_rn(l, rp) : __fmul_rn(l, rp);
    if (mb & 2u) x = __fsub_rn(x, pp);
  }
  return __fdiv_rn(x, tv);
}
/* FAST approx: reciprocal multiplies; |err| <= ~2e-6*|x| + 2e-5 */
__device__ __forceinline__ float xfast(float l, unsigned mb, float rp, float rrp,
                                       float pp, float rtv){
  float x = l;
  if (mb){
    x = (l > 0.f) ? l*rrp : l*rp;
    if (mb & 2u) x -= pp;
  }
  return x * rtv;
}
__device__ __forceinline__ unsigned mask8(const unsigned* __restrict__ pk, int i){
  unsigned w = pk[i >> 2];
  return (w >> ((i & 3) << 3)) & 0xFFu;
}

__global__ void k_init(){
  size_t i0 = (size_t)blockIdx.x*blockDim.x + threadIdx.x;
  size_t n = (size_t)NB*NW;
  for (size_t i = i0; i < n; i += (size_t)gridDim.x*blockDim.x) g_pk[i] = 0u;
  if (i0 < NB) g_candcnt[i0] = 0;
}

__global__ void k_scatter(const int* __restrict__ toks, int L, unsigned bit){
  int i = blockIdx.x*blockDim.x + threadIdx.x;
  if (i >= NB*L) return;
  int row = i / L;
  int t = toks[i];
  if (t >= 0 && t < NV)
    atomicOr(&g_pk[(size_t)row*NW + (t >> 4)], bit << ((t & 15)*2));
}

/* fused chunk-max + superset candidate collection (approx compare, exact store) */
__global__ __launch_bounds__(256) void k_pass1(
  const float* __restrict__ logits, const float* __restrict__ presence,
  const float* __restrict__ rep, const float* __restrict__ temp)
{
  __shared__ float s_red[8];
  __shared__ float s_bmax;
  __shared__ float sb_v[SBUF];
  __shared__ int   sb_i[SBUF];
  __shared__ unsigned sb_n;
  __shared__ unsigned sb_base;

  int row = blockIdx.y;
  float rp = rep[row], pp = presence[row];
  float tv = temp[row]; if (tv < SEPS) tv = 1.f;
  float rrp = __fdividef(1.f, rp), rtv = __fdividef(1.f, tv);
  int base = blockIdx.x*CHUNK4;
  const float4* l4 = ((const float4*)(logits + (size_t)row*NV)) + base;
  const unsigned* pkrow = g_pk + (size_t)row*NW;

  if (threadIdx.x == 0) sb_n = 0;

  float mymax = -INFINITY;
  for (int i = threadIdx.x; i < CHUNK4; i += 256){
    float4 l = l4[i];
    unsigned m8 = mask8(pkrow, base + i);
    float a = xfast(l.x, (m8     )&3u, rp, rrp, pp, rtv);
    float b = xfast(l.y, (m8 >> 2)&3u, rp, rrp, pp, rtv);
    float c = xfast(l.z, (m8 >> 4)&3u, rp, rrp, pp, rtv);
    float d = xfast(l.w, (m8 >> 6)&3u, rp, rrp, pp, rtv);
    mymax = fmaxf(fmaxf(mymax, fmaxf(a, b)), fmaxf(c, d));
  }
  #pragma unroll
  for (int o = 16; o > 0; o >>= 1) mymax = fmaxf(mymax, __shfl_xor_sync(0xFFFFFFFFu, mymax, o));
  if ((threadIdx.x & 31) == 0) s_red[threadIdx.x >> 5] = mymax;
  __syncthreads();
  if (threadIdx.x == 0){
    float v = s_red[0];
    #pragma unroll
    for (int w = 1; w < 8; w++) v = fmaxf(v, s_red[w]);
    s_bmax = v;
  }
  __syncthreads();
  float cut = cutf(s_bmax) - CUTMARG;   /* margin covers approx error */

  for (int i = threadIdx.x; i < CHUNK4; i += 256){
    float4 l = l4[i];                                   /* L1/L2 hit */
    unsigned m8 = mask8(pkrow, base + i);
    float v[4];
    v[0] = xfast(l.x, (m8     )&3u, rp, rrp, pp, rtv);
    v[1] = xfast(l.y, (m8 >> 2)&3u, rp, rrp, pp, rtv);
    v[2] = xfast(l.z, (m8 >> 4)&3u, rp, rrp, pp, rtv);
    v[3] = xfast(l.w, (m8 >> 6)&3u, rp, rrp, pp, rtv);
    float lv[4] = {l.x, l.y, l.z, l.w};
    #pragma unroll
    for (int j = 0; j < 4; j++){
      if (v[j] >= cut){
        float ex = xform(lv[j], (m8 >> (2*j))&3u, rp, pp, tv);  /* EXACT, rare */
        unsigned id = atomicAdd(&sb_n, 1u);
        if (id < SBUF){ sb_v[id] = ex; sb_i[id] = (base + i)*4 + j; }
        else {
          int p = atomicAdd(&g_candcnt[row], 1);
          if (p < CAP){ g_cand[row*CAP + p] = ex; g_cidx[row*CAP + p] = (base + i)*4 + j; }
        }
      }
    }
  }
  __syncthreads();
  unsigned n = sb_n; if (n > SBUF) n = SBUF;
  if (threadIdx.x == 0) sb_base = (unsigned)atomicAdd(&g_candcnt[row], (int)n);
  __syncthreads();
  unsigned b0 = sb_base;
  for (unsigned i = threadIdx.x; i < n; i += 256){
    unsigned p = b0 + i;
    if (p < CAP){ g_cand[row*CAP + p] = sb_v[i]; g_cidx[row*CAP + p] = sb_i[i]; }
  }
}

__global__ __launch_bounds__(256) void k_select(
  const float* __restrict__ logits, const float* __restrict__ presence,
  const float* __restrict__ rep, const float* __restrict__ temp,
  const int* __restrict__ topk, const float* __restrict__ topp)
{
  __shared__ unsigned s_hist[256];
  __shared__ float s_small[SCAP];
  __shared__ float s_e[SCAP];
  __shared__ double s_d[SCAP];
  __shared__ unsigned s_cnt;
  __shared__ unsigned s_maxu;
  __shared__ int s_sel, s_want, s_jstar;

  int row = blockIdx.x, tid = threadIdx.x;
  int kneed = topk[row]; if (kneed < 1) kneed = 1; if (kneed > NV) kneed = NV;
  float tp = topp[row];
  int count = g_candcnt[row];
  float* cand = g_cand + row*CAP;
  int* cidx = g_cidx + row*CAP;

  /* exact row max from exact candidates */
  if (tid == 0) s_maxu = 0u;
  __syncthreads();
  {
    int c0 = count > CAP ? CAP : count;
    float lm = -INFINITY;
    for (int i = tid; i < c0; i += 256) lm = fmaxf(lm, cand[i]);
    #pragma unroll
    for (int o = 16; o > 0; o >>= 1) lm = fmaxf(lm, __shfl_xor_sync(0xFFFFFFFFu, lm, o));
    if ((tid & 31) == 0) atomicMax(&s_maxu, ofl(lm));
  }
  __syncthreads();
  float M = ifl(s_maxu);

  if (!(count >= kneed && count <= CAP)){
    /* fallback: bracketed exact search (cold path) */
    float rp = rep[row], pp = presence[row];
    float tv = temp[row]; if (tv < SEPS) tv = 1.f;
    const float4* l4 = (const float4*)(logits + (size_t)row*NV);
    const unsigned* pkrow = g_pk + (size_t)row*NW;
    float delta = 0.38f*fabsf(M) + 0.5f;
    float dlo = 0.f, dhi = -1.f;
    if (count < kneed){ dlo = delta; delta *= 2.f; }
    else              { dhi = delta; delta *= 0.5f; }
    for (int it = 0; it < 64; it++){
      float c2 = M - delta;
      if (tid == 0) s_cnt = 0;
      __syncthreads();
      for (int i = tid; i < N4; i += 256){
        float4 l = l4[i];
        unsigned m8 = mask8(pkrow, i);
        float v[4];
        v[0] = xform(l.x, (m8     )&3u, rp, pp, tv);
        v[1] = xform(l.y, (m8 >> 2)&3u, rp, pp, tv);
        v[2] = xform(l.z, (m8 >> 4)&3u, rp, pp, tv);
        v[3] = xform(l.w, (m8 >> 6)&3u, rp, pp, tv);
        #pragma unroll
        for (int j = 0; j < 4; j++){
          if (v[j] >= c2){
            unsigned id = atomicAdd(&s_cnt, 1u);
            if (id < CAP){ cand[id] = v[j]; cidx[id] = i*4 + j; }
          }
        }
      }
      __syncthreads();
      count = (int)s_cnt;
      __syncthreads();
      if (count >= kneed && count <= CAP) break;
      if (count < kneed){ dlo = delta; delta = (dhi > 0.f) ? 0.5f*(delta + dhi) : delta*2.f; }
      else              { dhi = delta; delta = 0.5f*(dlo + delta); }
    }
    if (count > CAP) count = CAP;
    if (count < kneed) kneed = count;
    /* refresh exact max over final list */
    if (tid == 0) s_maxu = 0u;
    __syncthreads();
    float lm = -INFINITY;
    for (int i = tid; i < count; i += 256) lm = fmaxf(lm, cand[i]);
    #pragma unroll
    for (int o = 16; o > 0; o >>= 1) lm = fmaxf(lm, __shfl_xor_sync(0xFFFFFFFFu, lm, o));
    if ((tid & 31) == 0) atomicMax(&s_maxu, ofl(lm));
    __syncthreads();
    M = ifl(s_maxu);
  }
  __syncthreads();

  /* radix-select k-th largest value (exact values) */
  unsigned prefix = 0; int want = kneed;
  for (int shift = 24; shift >= 0; shift -= 8){
    s_hist[tid] = 0;
    __syncthreads();
    unsigned himask = (shift == 24) ? 0u : (0xFFFFFFFFu << (shift + 8));
    for (int i = tid; i < count; i += 256){
      unsigned ou = ofl(cand[i]);
      if ((ou & himask) == prefix) atomicAdd(&s_hist[(ou >> shift) & 255u], 1u);
    }
    __syncthreads();
    if (tid == 0){
      int c = 0, b = 255;
      for (; b > 0; b--){
        int h = (int)s_hist[b];
        if (c + h >= want) break;
        c += h;
      }
      s_sel = b; s_want = want - c;
    }
    __syncthreads();
    prefix |= ((unsigned)s_sel) << shift;
    want = s_want;
    __syncthreads();
  }
  float thr = ifl(prefix);

  /* gather survivors >= thr */
  if (tid == 0) s_cnt = 0;
  __syncthreads();
  for (int i = tid; i < count; i += 256){
    float v = cand[i];
    if (v >= thr){
      unsigned id = atomicAdd(&s_cnt, 1u);
      if (id < SCAP) s_small[id] = v;
    }
  }
  __syncthreads();
  int m = (int)s_cnt; if (m > SCAP) m = SCAP;
  if (tid >= m) s_small[tid] = -INFINITY;
  __syncthreads();

  /* bitonic sort descending */
  for (int k = 2; k <= SCAP; k <<= 1){
    for (int j = k >> 1; j > 0; j >>= 1){
      int ixj = tid ^ j;
      if (ixj > tid){
        float a = s_small[tid], b = s_small[ixj];
        bool desc = ((tid & k) == 0);
        if (desc ? (a < b) : (a > b)){ s_small[tid] = b; s_small[ixj] = a; }
      }
      __syncthreads();
    }
  }
  float ex_tiny = expf(__fsub_rn(TINYV, M));
  s_e[tid] = (tid < m) ? expf(s_small[tid] - M) : 0.f;
  __syncthreads();

  /* parallel suffix sums */
  s_d[tid] = (double)s_e[tid];
  __syncthreads();
  #pragma unroll
  for (int off = 1; off < SCAP; off <<= 1){
    double add = (tid + off < SCAP) ? s_d[tid + off] : 0.0;
    __syncthreads();
    s_d[tid] += add;
    __syncthreads();
  }
  double T = (double)(NV - m) * (double)ex_tiny;
  double Z1 = T + s_d[0];
  double need = (double)__fsub_rn(1.0f, tp) * Z1;
  if (tid == 0) s_jstar = 0;
  __syncthreads();
  if (tid < m && (T + s_d[tid]) > need) atomicMax(&s_jstar, tid);
  __syncthreads();

  if (tid == 0){
    int jstar = s_jstar;
    float thrf = s_small[jstar];
    int nsel = jstar + 1;

    /* tie handling at top-p boundary (stable argsort keeps larger token idx) */
    int lo = jstar;
    while (lo > 0 && s_small[lo-1] == thrf) lo--;
    int q = jstar - lo + 1;
    int dcnt = 0;
    for (int i = jstar; i < m && s_small[i] == thrf; i++) dcnt++;
    dcnt += q - 1;
    int idx_cut = INT_MIN;
    if (q < dcnt){
      int idxs[64]; int dt = 0;
      for (int i = 0; i < count && dt < 64; i++)
        if (cand[i] == thrf) idxs[dt++] = cidx[i];
      if (q < dt){
        for (int a = 0; a < q; a++){
          int best = a;
          for (int b2 = a+1; b2 < dt; b2++) if (idxs[b2] > idxs[best]) best = b2;
          int t2 = idxs[a]; idxs[a] = idxs[best]; idxs[best] = t2;
        }
        idx_cut = idxs[q-1];
      }
    }

    double Zsel = s_d[0] - ((jstar+1 < SCAP) ? s_d[jstar+1] : 0.0);
    double Z2 = (double)(NV - nsel) * (double)ex_tiny + Zsel;
    float Z2f = (float)Z2;
    float invZ2 = 1.0f / Z2f;
    g_params[row*8+0] = thrf;
    g_params[row*8+1] = M;
    g_params[row*8+2] = invZ2;
    g_params[row*8+3] = __fdiv_rn(ex_tiny, Z2f);
    g_params[row*8+4] = __int_as_float(idx_cut);
  }
}

__global__ __launch_bounds__(256) void k_out(
  const float* __restrict__ logits, const float* __restrict__ presence,
  const float* __restrict__ rep, const float* __restrict__ temp,
  float* __restrict__ out, int mode)
{
  int row = blockIdx.y;
  float thrf = g_params[row*8+0], M2 = g_params[row*8+1];
  float invZ2 = g_params[row*8+2], tinyP = g_params[row*8+3];
  int idx_cut = __float_as_int(g_params[row*8+4]);
  float rp = rep[row], pp = presence[row];
  float tv = temp[row]; if (tv < SEPS) tv = 1.f;
  float rrp = __fdividef(1.f, rp), rtv = __fdividef(1.f, tv);
  float tlo = thrf - 2e-5f;                 /* eps band lower edge */
  int base = blockIdx.x*CHUNK4;
  const float4* l4 = ((const float4*)(logits + (size_t)row*NV)) + base;
  const unsigned* pkrow = g_pk + (size_t)row*NW;
  float4* o4 = ((float4*)(out + (size_t)row*NV)) + base;

  for (int i = threadIdx.x; i < CHUNK4; i += 256){
    unsigned m8 = mask8(pkrow, base + i);
    float4 l = l4[i];
    float v[4];
    v[0] = xfast(l.x, (m8     )&3u, rp, rrp, pp, rtv);
    v[1] = xfast(l.y, (m8 >> 2)&3u, rp, rrp, pp, rtv);
    v[2] = xfast(l.z, (m8 >> 4)&3u, rp, rrp, pp, rtv);
    v[3] = xfast(l.w, (m8 >> 6)&3u, rp, rrp, pp, rtv);
    float lv[4] = {l.x, l.y, l.z, l.w};
    /* maybe-selected if approx value + error bound crosses band edge */
    bool mb0 = fmaf(fabsf(v[0]), 2e-6f, v[0]) >= tlo;
    bool mb1 = fmaf(fabsf(v[1]), 2e-6f, v[1]) >= tlo;
    bool mb2 = fmaf(fabsf(v[2]), 2e-6f, v[2]) >= tlo;
    bool mb3 = fmaf(fabsf(v[3]), 2e-6f, v[3]) >= tlo;
    float4 r = make_float4(tinyP, tinyP, tinyP, tinyP);
    if (__any_sync(__activemask(), mb0 | mb1 | mb2 | mb3)){
      int gi = (base + i)*4;
      float* rr = &r.x;
      #pragma unroll
      for (int j = 0; j < 4; j++){
        bool mj = (j==0) ? mb0 : (j==1) ? mb1 : (j==2) ? mb2 : mb3;
        if (mj){
          float ex = xform(lv[j], (m8 >> (2*j))&3u, rp, pp, tv);  /* EXACT */
          if ((ex > thrf) || (ex == thrf && gi + j >= idx_cut))
            rr[j] = expf(ex - M2) * invZ2;
        }
      }
    }
    o4[i] = r;

    if (mode == 1){
      float4 pm, om;
      pm.x = (m8 & 0x01u) ? 1.f : 0.f;  om.x = (m8 & 0x02u) ? 1.f : 0.f;
      pm.y = (m8 & 0x04u) ? 1.f : 0.f;  om.y = (m8 & 0x08u) ? 1.f : 0.f;
      pm.z = (m8 & 0x10u) ? 1.f : 0.f;  om.z = (m8 & 0x20u) ? 1.f : 0.f;
      pm.w = (m8 & 0x40u) ? 1.f : 0.f;  om.w = (m8 & 0x80u) ? 1.f : 0.f;
      (((float4*)(out + (size_t)NB*NV)) + (size_t)row*N4)[base + i] = pm;
      (((float4*)(out + 2*(size_t)NB*NV)) + (size_t)row*N4)[base + i] = om;
    } else if (mode == 2){
      uchar4 pm, om;
      pm.x = (m8 & 0x01u) ? 1 : 0;  om.x = (m8 & 0x02u) ? 1 : 0;
      pm.y = (m8 & 0x04u) ? 1 : 0;  om.y = (m8 & 0x08u) ? 1 : 0;
      pm.z = (m8 & 0x10u) ? 1 : 0;  om.z = (m8 & 0x20u) ? 1 : 0;
      pm.w = (m8 & 0x40u) ? 1 : 0;  om.w = (m8 & 0x80u) ? 1 : 0;
      unsigned char* bp = (unsigned char*)out + (size_t)NB*NV*4;
      ((uchar4*)(bp + (size_t)row*NV))[base + i] = pm;
      ((uchar4*)(bp + (size_t)NB*NV + (size_t)row*NV))[base + i] = om;
    }
  }
}

extern "C" void kernel_launch(void* const* d_in, const int* in_sizes, int n_in,
                              void* d_out, int out_size) {
  /* size-based input resolution (robust to dict vs alphabetical metadata order) */
  int il = -1, t0 = -1, t1 = -1;
  for (int i = 0; i < n_in; i++){
    if (in_sizes[i] == NB*NV && il < 0) il = i;
    else if (in_sizes[i] > NB){ if (t0 < 0) t0 = i; else t1 = i; }
  }
  int ip, io;
  if (in_sizes[t0] >= in_sizes[t1]){ ip = t0; io = t1; } else { ip = t1; io = t0; }
  int s[6], ns = 0;
  for (int i = 0; i < n_in; i++)
    if (i != il && i != ip && i != io && ns < 6) s[ns++] = i;
  int ipres = (ip < io) ? s[0] : s[1];
  int irep = s[2], itemp = s[3], itopk = s[4], itopp = s[5];

  const float* logits = (const float*)d_in[il];
  const int*   ptoks  = (const int*)d_in[ip];
  const int*   otoks  = (const int*)d_in[io];
  const float* pres   = (const float*)d_in[ipres];
  const float* rep    = (const float*)d_in[irep];
  const float* temp   = (const float*)d_in[itemp];
  const int*   tk     = (const int*)d_in[itopk];
  const float* tp     = (const float*)d_in[itopp];
  float* out = (float*)d_out;

  int PL = in_sizes[ip] / NB;
  int OL = in_sizes[io] / NB;

  long long bv = (long long)NB * NV;
  int mode = 0;
  if ((long long)out_size >= 3*bv) mode = 1;                 /* masks as float */
  else if ((long long)out_size >= bv + bv/2) mode = 2;       /* masks as bytes */

  k_init<<<512, 256>>>();
  k_scatter<<<(NB*PL + 255)/256, 256>>>(ptoks, PL, 1u);
  k_scatter<<<(NB*OL + 255)/256, 256>>>(otoks, OL, 2u);
  dim3 grid(BPR, NB);
  k_pass1<<<grid, 256>>>(logits, pres, rep, temp);
  k_select<<<NB, 256>>>(logits, pres, rep, temp, tk, tp);
  k_out<<<grid, 256>>>(logits, pres, rep, temp, out, mode);
}